// round 2
// baseline (speedup 1.0000x reference)
#include <cuda_runtime.h>

#define N_NODES 50000
#define N_EDGES 800000
#define IN_CH   64
#define HC      128      // HEADS * OUT_CH
#define HEADS   4
#define NEG_SLOPE 0.2f
#define BN_EPS  1e-5f

// ---------------- static device scratch (no runtime allocation) ----------------
__device__ float g_xl[N_NODES * HC];        // 25.6 MB
__device__ float g_xr[N_NODES * HC];        // 25.6 MB
__device__ int   g_src[N_EDGES];
__device__ int   g_dst[N_EDGES];
__device__ int   g_count[N_NODES];
__device__ int   g_off[N_NODES + 1];
__device__ int   g_cursor[N_NODES];
__device__ int   g_csr_src[N_EDGES];        // 3.2 MB
__device__ float g_attr_sum[3];
__device__ float g_mean[3];
__device__ float g_chansum[HC];
__device__ float g_chansq[HC];

// ---------------- K0: init scratch ----------------
__global__ void k_init() {
    int i = blockIdx.x * blockDim.x + threadIdx.x;
    if (i < N_NODES) g_count[i] = 0;
    if (i < 3)       g_attr_sum[i] = 0.f;
    if (i < HC)      { g_chansum[i] = 0.f; g_chansq[i] = 0.f; }
}

// ---------------- K0b: normalize edge_index dtype (int64 vs int32) ----------------
// If the buffer holds little-endian int64 values < 2^31, every odd 32-bit word
// is zero. Random int32 indices in [0,50000) make 128 consecutive zero odd
// words essentially impossible. Detection is deterministic per block.
__global__ void k_convert(const int* __restrict__ ei_raw) {
    __shared__ int is64;
    if (threadIdx.x == 0) {
        int z = 1;
        for (int j = 1; j < 256; j += 2)
            if (ei_raw[j] != 0) { z = 0; break; }
        is64 = z;
    }
    __syncthreads();
    int stride = gridDim.x * blockDim.x;
    if (is64) {
        for (int e = blockIdx.x * blockDim.x + threadIdx.x; e < N_EDGES; e += stride) {
            g_src[e] = ei_raw[2 * e];                    // low word of ei[0][e]
            g_dst[e] = ei_raw[2 * (N_EDGES + e)];        // low word of ei[1][e]
        }
    } else {
        for (int e = blockIdx.x * blockDim.x + threadIdx.x; e < N_EDGES; e += stride) {
            g_src[e] = ei_raw[e];
            g_dst[e] = ei_raw[N_EDGES + e];
        }
    }
}

// ---------------- K1: xl = x@Wl, xr = x@Wr (fused) ----------------
__global__ void k_gemm(const float* __restrict__ x,
                       const float* __restrict__ Wl,
                       const float* __restrict__ Wr) {
    __shared__ float xs[4][IN_CH];
    int node0 = blockIdx.x * 4;
    int t = threadIdx.x;
    xs[t >> 6][t & 63] = x[(node0 + (t >> 6)) * IN_CH + (t & 63)];
    __syncthreads();

    const float* W  = (t < HC) ? Wl : Wr;
    float*       dst = (t < HC) ? g_xl : g_xr;
    int c = t & (HC - 1);

    float a0 = 0.f, a1 = 0.f, a2 = 0.f, a3 = 0.f;
#pragma unroll
    for (int k = 0; k < IN_CH; k++) {
        float w = W[k * HC + c];
        a0 += xs[0][k] * w;
        a1 += xs[1][k] * w;
        a2 += xs[2][k] * w;
        a3 += xs[3][k] * w;
    }
    dst[(node0 + 0) * HC + c] = a0;
    dst[(node0 + 1) * HC + c] = a1;
    dst[(node0 + 2) * HC + c] = a2;
    dst[(node0 + 3) * HC + c] = a3;
}

// ---------------- K2: edge_attr sum (for mean) + in-degree histogram ----------------
__global__ void k_edge_stats(const float* __restrict__ pos) {
    float s0 = 0.f, s1 = 0.f, s2 = 0.f;
    int stride = gridDim.x * blockDim.x;
    for (int e = blockIdx.x * blockDim.x + threadIdx.x; e < N_EDGES; e += stride) {
        int s = g_src[e];
        int d = g_dst[e];
        s0 += pos[s * 3 + 0] - pos[d * 3 + 0];
        s1 += pos[s * 3 + 1] - pos[d * 3 + 1];
        s2 += pos[s * 3 + 2] - pos[d * 3 + 2];
        atomicAdd(&g_count[d], 1);
    }
    __shared__ float red[3][8];
#pragma unroll
    for (int m = 16; m; m >>= 1) {
        s0 += __shfl_xor_sync(0xffffffffu, s0, m);
        s1 += __shfl_xor_sync(0xffffffffu, s1, m);
        s2 += __shfl_xor_sync(0xffffffffu, s2, m);
    }
    int w = threadIdx.x >> 5, l = threadIdx.x & 31;
    if (l == 0) { red[0][w] = s0; red[1][w] = s1; red[2][w] = s2; }
    __syncthreads();
    if (threadIdx.x < 3) {
        float t = 0.f;
        int nw = blockDim.x >> 5;
        for (int j = 0; j < nw; j++) t += red[threadIdx.x][j];
        atomicAdd(&g_attr_sum[threadIdx.x], t);
    }
}

// ---------------- K3: exclusive scan of counts -> offsets; mean_attr ----------------
__global__ void k_scan() {
    const int T = 1024;
    const int ITEMS = (N_NODES + T - 1) / T;   // 49
    __shared__ int ssum[T];
    int t = threadIdx.x;
    int base = t * ITEMS;
    int local = 0;
    for (int j = 0; j < ITEMS; j++) {
        int i = base + j;
        if (i < N_NODES) local += g_count[i];
    }
    ssum[t] = local;
    __syncthreads();
    for (int d = 1; d < T; d <<= 1) {
        int v = (t >= d) ? ssum[t - d] : 0;
        __syncthreads();
        ssum[t] += v;
        __syncthreads();
    }
    int run = ssum[t] - local;
    for (int j = 0; j < ITEMS; j++) {
        int i = base + j;
        if (i < N_NODES) {
            g_off[i] = run;
            g_cursor[i] = run;
            run += g_count[i];
        }
    }
    if (t == T - 1) g_off[N_NODES] = ssum[T - 1];
    if (t == 0) {
        float inv = 1.0f / (float)N_EDGES;
        g_mean[0] = g_attr_sum[0] * inv;
        g_mean[1] = g_attr_sum[1] * inv;
        g_mean[2] = g_attr_sum[2] * inv;
    }
}

// ---------------- K4: scatter edges into CSR-by-dst ----------------
__global__ void k_scatter() {
    int stride = gridDim.x * blockDim.x;
    for (int e = blockIdx.x * blockDim.x + threadIdx.x; e < N_EDGES; e += stride) {
        int p = atomicAdd(&g_cursor[g_dst[e]], 1);
        g_csr_src[p] = g_src[e];
    }
}

// ---------------- K5: per-node GATv2 softmax + aggregation + stats ----------------
// One warp per destination node. Lane handles 4 consecutive channels (float4).
__device__ __forceinline__ float edge_partial(float4 xl4, float4 xr4,
                                              float d0, float d1, float d2,
                                              float4 we0, float4 we1, float4 we2,
                                              float4 at4) {
    float e0 = xl4.x + xr4.x + d0 * we0.x + d1 * we1.x + d2 * we2.x;
    float e1 = xl4.y + xr4.y + d0 * we0.y + d1 * we1.y + d2 * we2.y;
    float e2 = xl4.z + xr4.z + d0 * we0.z + d1 * we1.z + d2 * we2.z;
    float e3 = xl4.w + xr4.w + d0 * we0.w + d1 * we1.w + d2 * we2.w;
    e0 = (e0 > 0.f) ? e0 : NEG_SLOPE * e0;
    e1 = (e1 > 0.f) ? e1 : NEG_SLOPE * e1;
    e2 = (e2 > 0.f) ? e2 : NEG_SLOPE * e2;
    e3 = (e3 > 0.f) ? e3 : NEG_SLOPE * e3;
    return e0 * at4.x + e1 * at4.y + e2 * at4.z + e3 * at4.w;
}

__global__ void k_aggregate(const float* __restrict__ pos,
                            const float* __restrict__ W_edge,
                            const float* __restrict__ att,
                            float* __restrict__ out) {
    __shared__ float ssum[HC], ssq[HC];
    if (threadIdx.x < HC) { ssum[threadIdx.x] = 0.f; ssq[threadIdx.x] = 0.f; }
    __syncthreads();

    int warp = (blockIdx.x * blockDim.x + threadIdx.x) >> 5;  // == node id (exact grid)
    int lane = threadIdx.x & 31;
    int i = warp;
    int c4 = lane * 4;

    float4 xr4 = *(const float4*)(g_xr + i * HC + c4);
    float4 at4 = *(const float4*)(att + c4);
    float4 we0 = *(const float4*)(W_edge + 0 * HC + c4);
    float4 we1 = *(const float4*)(W_edge + 1 * HC + c4);
    float4 we2 = *(const float4*)(W_edge + 2 * HC + c4);
    float pd0 = pos[i * 3 + 0], pd1 = pos[i * 3 + 1], pd2 = pos[i * 3 + 2];

    float4 acc = make_float4(0.f, 0.f, 0.f, 0.f);
    float denom = 0.f;

    int e0i = g_off[i], e1i = g_off[i + 1];
    for (int e = e0i; e < e1i; e++) {
        int s = g_csr_src[e];
        float4 xl4 = *(const float4*)(g_xl + s * HC + c4);
        float d0 = pos[s * 3 + 0] - pd0;
        float d1 = pos[s * 3 + 1] - pd1;
        float d2 = pos[s * 3 + 2] - pd2;
        float p = edge_partial(xl4, xr4, d0, d1, d2, we0, we1, we2, at4);
        p += __shfl_xor_sync(0xffffffffu, p, 1);
        p += __shfl_xor_sync(0xffffffffu, p, 2);
        p += __shfl_xor_sync(0xffffffffu, p, 4);
        float w = __expf(p);   // scores are O(1): max-subtraction unnecessary
        denom += w;
        acc.x += w * xl4.x;
        acc.y += w * xl4.y;
        acc.z += w * xl4.z;
        acc.w += w * xl4.w;
    }
    // self-loop with mean edge_attr
    {
        float4 xl4 = *(const float4*)(g_xl + i * HC + c4);
        float p = edge_partial(xl4, xr4, g_mean[0], g_mean[1], g_mean[2],
                               we0, we1, we2, at4);
        p += __shfl_xor_sync(0xffffffffu, p, 1);
        p += __shfl_xor_sync(0xffffffffu, p, 2);
        p += __shfl_xor_sync(0xffffffffu, p, 4);
        float w = __expf(p);
        denom += w;
        acc.x += w * xl4.x;
        acc.y += w * xl4.y;
        acc.z += w * xl4.z;
        acc.w += w * xl4.w;
    }

    float inv = 1.f / (denom + 1e-16f);
    float4 o = make_float4(acc.x * inv, acc.y * inv, acc.z * inv, acc.w * inv);
    *(float4*)(out + i * HC + c4) = o;

    atomicAdd(&ssum[c4 + 0], o.x);  atomicAdd(&ssq[c4 + 0], o.x * o.x);
    atomicAdd(&ssum[c4 + 1], o.y);  atomicAdd(&ssq[c4 + 1], o.y * o.y);
    atomicAdd(&ssum[c4 + 2], o.z);  atomicAdd(&ssq[c4 + 2], o.z * o.z);
    atomicAdd(&ssum[c4 + 3], o.w);  atomicAdd(&ssq[c4 + 3], o.w * o.w);
    __syncthreads();
    if (threadIdx.x < HC) {
        atomicAdd(&g_chansum[threadIdx.x], ssum[threadIdx.x]);
        atomicAdd(&g_chansq[threadIdx.x],  ssq[threadIdx.x]);
    }
}

// ---------------- K6: BatchNorm (training-mode batch stats) ----------------
__global__ void k_bn(float* __restrict__ out,
                     const float* __restrict__ gamma,
                     const float* __restrict__ beta) {
    int idx = blockIdx.x * blockDim.x + threadIdx.x;   // over N*HC/4 float4s
    if (idx >= N_NODES * HC / 4) return;
    int c4 = (idx * 4) & (HC - 1);
    const float invN = 1.0f / (float)N_NODES;
    float4 v = ((float4*)out)[idx];
    float r[4] = {v.x, v.y, v.z, v.w};
#pragma unroll
    for (int j = 0; j < 4; j++) {
        int c = c4 + j;
        float mu  = g_chansum[c] * invN;
        float var = g_chansq[c] * invN - mu * mu;
        r[j] = (r[j] - mu) * rsqrtf(var + BN_EPS) * gamma[c] + beta[c];
    }
    ((float4*)out)[idx] = make_float4(r[0], r[1], r[2], r[3]);
}

// ---------------- launch ----------------
extern "C" void kernel_launch(void* const* d_in, const int* in_sizes, int n_in,
                              void* d_out, int out_size) {
    const float* x     = (const float*)d_in[0];
    const float* pos   = (const float*)d_in[1];
    const int*   eiraw = (const int*)d_in[2];
    const float* Wl    = (const float*)d_in[3];
    const float* Wr    = (const float*)d_in[4];
    const float* We    = (const float*)d_in[5];
    const float* att   = (const float*)d_in[6];
    const float* gamma = (const float*)d_in[7];
    const float* beta  = (const float*)d_in[8];
    float* out = (float*)d_out;

    k_init<<<(N_NODES + 255) / 256, 256>>>();
    k_convert<<<1184, 256>>>(eiraw);
    k_gemm<<<N_NODES / 4, 256>>>(x, Wl, Wr);
    k_edge_stats<<<1184, 256>>>(pos);
    k_scan<<<1, 1024>>>();
    k_scatter<<<1184, 256>>>();
    k_aggregate<<<N_NODES / 8, 256>>>(pos, We, att, out);
    k_bn<<<(N_NODES * HC / 4 + 255) / 256, 256>>>(out, gamma, beta);
}